// round 9
// baseline (speedup 1.0000x reference)
#include <cuda_runtime.h>

// RipsLayer: pure gather of pairwise distances at given index pairs.
//
// Output layout (flattened tuple order, fp32):
//   [0, 2*F0)      finite_dgm0 rows: (0, dist)     -> float2 stores
//   [2*F0, +E0)    essential_dgm0: zeros
//   [.., +2*F1)    finite_dgm1 rows: (dist, dist)  -> scalar stores (odd base)
//   [.., +E1)      essential_dgm1: one dist per row
//
// Bottleneck model: L1tex wavefronts from scattered gathers. Each point row
// is 12B; load it with ONE float2 + ONE scalar LDG (parity-selected offsets,
// both 8B/4B aligned) instead of three scalar LDGs -> 33% fewer wavefronts.

__device__ __forceinline__ float3 load_pt(const float* __restrict__ X, int a) {
    // byte base of row a = 12*a. Even a: [x,y] @ +0 (8-aligned), z @ +8.
    // Odd  a: x @ +0, [y,z] @ +4 (24k+16 -> 8-aligned).
    const char* base = reinterpret_cast<const char*>(X) + 12u * (unsigned)a;
    bool odd = (a & 1);
    float2 v = __ldg(reinterpret_cast<const float2*>(base + (odd ? 4 : 0)));
    float  s = __ldg(reinterpret_cast<const float*>(base + (odd ? 0 : 8)));
    float3 r;
    r.x = odd ? s   : v.x;
    r.y = odd ? v.x : v.y;
    r.z = odd ? v.y : s;
    return r;
}

__device__ __forceinline__ float pair_dist(const float* __restrict__ X,
                                           int a, int b) {
    float3 pa = load_pt(X, a);
    float3 pb = load_pt(X, b);
    float dx = pa.x - pb.x;
    float dy = pa.y - pb.y;
    float dz = pa.z - pb.z;
    return sqrtf(fmaf(dx, dx, fmaf(dy, dy, dz * dz)));
}

__global__ void __launch_bounds__(128)
rips_layer_kernel(const float* __restrict__ X,
                  const int* __restrict__ idx0_finite,    // [F0,3]
                  const int* __restrict__ idx1_finite,    // [F1,4] 16B rows
                  const int* __restrict__ idx1_essential, // [E1,2]
                  float* __restrict__ out,
                  int F0, int E0, int F1, int E1) {
    int i = blockIdx.x * blockDim.x + threadIdx.x;

    const int T1 = F0;            // essential_dgm0 threads start
    const int T2 = T1 + E0;       // finite_dgm1 threads start
    const int T3 = T2 + F1;       // essential_dgm1 threads start
    const int total = T3 + E1;
    if (i >= total) return;

    const int o1 = 2 * F0;        // out: essential_dgm0 start
    const int o2 = o1 + E0;       // out: finite_dgm1 start
    const int o3 = o2 + 2 * F1;   // out: essential_dgm1 start

    if (i < T1) {
        // finite_dgm0 row i: (birth=0, death=dist(idx[3i+1], idx[3i+2]))
        int a = __ldg(idx0_finite + 3 * i + 1);
        int b = __ldg(idx0_finite + 3 * i + 2);
        float d = pair_dist(X, a, b);
        reinterpret_cast<float2*>(out)[i] = make_float2(0.0f, d);
    } else if (i < T2) {
        // essential_dgm0: zero
        out[o1 + (i - T1)] = 0.0f;
    } else if (i < T3) {
        // finite_dgm1 row j: indices (a0,b0,a1,b1) in one 16B load
        int j = i - T2;
        int4 idx = __ldg(reinterpret_cast<const int4*>(idx1_finite) + j);
        float d0 = pair_dist(X, idx.x, idx.y);
        float d1 = pair_dist(X, idx.z, idx.w);
        out[o2 + 2 * j + 0] = d0;   // odd base offset -> scalar stores
        out[o2 + 2 * j + 1] = d1;
    } else {
        // essential_dgm1 row k
        int k = i - T3;
        int a = __ldg(idx1_essential + 2 * k + 0);
        int b = __ldg(idx1_essential + 2 * k + 1);
        out[o3 + k] = pair_dist(X, a, b);
    }
}

extern "C" void kernel_launch(void* const* d_in, const int* in_sizes, int n_in,
                              void* d_out, int out_size) {
    const float* X              = (const float*)d_in[0];
    const int*   idx0_finite    = (const int*)d_in[1];
    // d_in[2] = idx0_essential — only its COUNT matters (zeros in output)
    const int*   idx1_finite    = (const int*)d_in[3];
    const int*   idx1_essential = (const int*)d_in[4];

    int F0 = in_sizes[1] / 3;   // idx0_finite [F0,3]
    int E0 = in_sizes[2];       // idx0_essential [E0]
    int F1 = in_sizes[3] / 4;   // idx1_finite [F1,4]
    int E1 = in_sizes[4] / 2;   // idx1_essential [E1,2]

    int total_threads = F0 + E0 + F1 + E1;

    const int threads = 128;    // best measured shape (R3: 4.58us)
    int blocks = (total_threads + threads - 1) / threads;
    rips_layer_kernel<<<blocks, threads>>>(
        X, idx0_finite, idx1_finite, idx1_essential,
        (float*)d_out, F0, E0, F1, E1);
}

// round 14
// speedup vs baseline: 1.0048x; 1.0048x over previous
#include <cuda_runtime.h>

// RipsLayer: pure gather of pairwise distances at given index pairs.
// (Measured-best configuration across R3/R4/R6/R8 ablations.)
//
// Output layout (flattened tuple order, fp32):
//   [0, 2*F0)      finite_dgm0 rows: (0, dist)     -> float2 stores
//   [2*F0, +E0)    essential_dgm0: zeros
//   [.., +2*F1)    finite_dgm1 rows: (dist, dist)  -> scalar stores (odd base)
//   [.., +E1)      essential_dgm1: one dist per row
//
// Floor analysis: bench flat at 6.62-6.66us across 4 kernel shapes; time is
// launch/graph overhead + one idx->X dependent L2 round-trip pair. 1 row per
// thread, 128-thread blocks (97 CTAs) is the measured optimum.

__device__ __forceinline__ float pair_dist(const float* __restrict__ X,
                                           int a, int b) {
    float ax = __ldg(X + 3 * a + 0);
    float ay = __ldg(X + 3 * a + 1);
    float az = __ldg(X + 3 * a + 2);
    float bx = __ldg(X + 3 * b + 0);
    float by = __ldg(X + 3 * b + 1);
    float bz = __ldg(X + 3 * b + 2);
    float dx = ax - bx;
    float dy = ay - by;
    float dz = az - bz;
    return sqrtf(fmaf(dx, dx, fmaf(dy, dy, dz * dz)));
}

__global__ void __launch_bounds__(128)
rips_layer_kernel(const float* __restrict__ X,
                  const int* __restrict__ idx0_finite,    // [F0,3]
                  const int* __restrict__ idx1_finite,    // [F1,4] 16B rows
                  const int* __restrict__ idx1_essential, // [E1,2]
                  float* __restrict__ out,
                  int F0, int E0, int F1, int E1) {
    int i = blockIdx.x * blockDim.x + threadIdx.x;

    const int T1 = F0;            // essential_dgm0 threads start
    const int T2 = T1 + E0;       // finite_dgm1 threads start
    const int T3 = T2 + F1;       // essential_dgm1 threads start
    const int total = T3 + E1;
    if (i >= total) return;

    const int o1 = 2 * F0;        // out: essential_dgm0 start
    const int o2 = o1 + E0;       // out: finite_dgm1 start
    const int o3 = o2 + 2 * F1;   // out: essential_dgm1 start

    if (i < T1) {
        // finite_dgm0 row i: (birth=0, death=dist(idx[3i+1], idx[3i+2]))
        int a = __ldg(idx0_finite + 3 * i + 1);
        int b = __ldg(idx0_finite + 3 * i + 2);
        float d = pair_dist(X, a, b);
        reinterpret_cast<float2*>(out)[i] = make_float2(0.0f, d);
    } else if (i < T2) {
        // essential_dgm0: zero
        out[o1 + (i - T1)] = 0.0f;
    } else if (i < T3) {
        // finite_dgm1 row j: indices (a0,b0,a1,b1) in one 16B load
        int j = i - T2;
        int4 idx = __ldg(reinterpret_cast<const int4*>(idx1_finite) + j);
        float d0 = pair_dist(X, idx.x, idx.y);
        float d1 = pair_dist(X, idx.z, idx.w);
        out[o2 + 2 * j + 0] = d0;   // odd base offset -> scalar stores
        out[o2 + 2 * j + 1] = d1;
    } else {
        // essential_dgm1 row k
        int k = i - T3;
        int a = __ldg(idx1_essential + 2 * k + 0);
        int b = __ldg(idx1_essential + 2 * k + 1);
        out[o3 + k] = pair_dist(X, a, b);
    }
}

extern "C" void kernel_launch(void* const* d_in, const int* in_sizes, int n_in,
                              void* d_out, int out_size) {
    const float* X              = (const float*)d_in[0];
    const int*   idx0_finite    = (const int*)d_in[1];
    // d_in[2] = idx0_essential — only its COUNT matters (zeros in output)
    const int*   idx1_finite    = (const int*)d_in[3];
    const int*   idx1_essential = (const int*)d_in[4];

    int F0 = in_sizes[1] / 3;   // idx0_finite [F0,3]
    int E0 = in_sizes[2];       // idx0_essential [E0]
    int F1 = in_sizes[3] / 4;   // idx1_finite [F1,4]
    int E1 = in_sizes[4] / 2;   // idx1_essential [E1,2]

    int total_threads = F0 + E0 + F1 + E1;

    const int threads = 128;    // measured optimum (R3: 4.58us / 6.62us)
    int blocks = (total_threads + threads - 1) / threads;
    rips_layer_kernel<<<blocks, threads>>>(
        X, idx0_finite, idx1_finite, idx1_essential,
        (float*)d_out, F0, E0, F1, E1);
}

// round 16
// speedup vs baseline: 1.0097x; 1.0049x over previous
#include <cuda_runtime.h>

// RipsLayer: pure gather of pairwise distances at given index pairs.
// FINAL — measured floor configuration.
//
// The reference materializes an 8192x8192 distance matrix; the outputs only
// gather ~16K distances at given index pairs, so this kernel computes exactly
// those. Ablation history (kernel us / bench us):
//   1 row/thr blk128 (this):  4.58-4.99 / 6.62   <- best, bench pinned
//   2 rows/thr blk128:        5.12      / 6.66
//   1 row/thr blk96:          4.64      / 6.62
//   parity-vectorized loads:  4.99      / 6.66
// Bench is launch/graph-overhead bound (~6.6us) + one irreducible dependent
// idx->X L2 round-trip pair; all pipes <4%, issue ~2%. Structural floor.
//
// Output layout (flattened tuple order, fp32):
//   [0, 2*F0)      finite_dgm0 rows: (0, dist)     -> float2 stores
//   [2*F0, +E0)    essential_dgm0: zeros
//   [.., +2*F1)    finite_dgm1 rows: (dist, dist)  -> scalar stores (odd base)
//   [.., +E1)      essential_dgm1: one dist per row

__device__ __forceinline__ float pair_dist(const float* __restrict__ X,
                                           int a, int b) {
    float ax = __ldg(X + 3 * a + 0);
    float ay = __ldg(X + 3 * a + 1);
    float az = __ldg(X + 3 * a + 2);
    float bx = __ldg(X + 3 * b + 0);
    float by = __ldg(X + 3 * b + 1);
    float bz = __ldg(X + 3 * b + 2);
    float dx = ax - bx;
    float dy = ay - by;
    float dz = az - bz;
    return sqrtf(fmaf(dx, dx, fmaf(dy, dy, dz * dz)));
}

__global__ void __launch_bounds__(128)
rips_layer_kernel(const float* __restrict__ X,
                  const int* __restrict__ idx0_finite,    // [F0,3]
                  const int* __restrict__ idx1_finite,    // [F1,4] 16B rows
                  const int* __restrict__ idx1_essential, // [E1,2]
                  float* __restrict__ out,
                  int F0, int E0, int F1, int E1) {
    int i = blockIdx.x * blockDim.x + threadIdx.x;

    const int T1 = F0;            // essential_dgm0 threads start
    const int T2 = T1 + E0;       // finite_dgm1 threads start
    const int T3 = T2 + F1;       // essential_dgm1 threads start
    const int total = T3 + E1;
    if (i >= total) return;

    const int o1 = 2 * F0;        // out: essential_dgm0 start
    const int o2 = o1 + E0;       // out: finite_dgm1 start
    const int o3 = o2 + 2 * F1;   // out: essential_dgm1 start

    if (i < T1) {
        // finite_dgm0 row i: (birth=0, death=dist(idx[3i+1], idx[3i+2]))
        int a = __ldg(idx0_finite + 3 * i + 1);
        int b = __ldg(idx0_finite + 3 * i + 2);
        float d = pair_dist(X, a, b);
        reinterpret_cast<float2*>(out)[i] = make_float2(0.0f, d);
    } else if (i < T2) {
        // essential_dgm0: zero
        out[o1 + (i - T1)] = 0.0f;
    } else if (i < T3) {
        // finite_dgm1 row j: indices (a0,b0,a1,b1) in one 16B load
        int j = i - T2;
        int4 idx = __ldg(reinterpret_cast<const int4*>(idx1_finite) + j);
        float d0 = pair_dist(X, idx.x, idx.y);
        float d1 = pair_dist(X, idx.z, idx.w);
        out[o2 + 2 * j + 0] = d0;   // odd base offset -> scalar stores
        out[o2 + 2 * j + 1] = d1;
    } else {
        // essential_dgm1 row k
        int k = i - T3;
        int a = __ldg(idx1_essential + 2 * k + 0);
        int b = __ldg(idx1_essential + 2 * k + 1);
        out[o3 + k] = pair_dist(X, a, b);
    }
}

extern "C" void kernel_launch(void* const* d_in, const int* in_sizes, int n_in,
                              void* d_out, int out_size) {
    const float* X              = (const float*)d_in[0];
    const int*   idx0_finite    = (const int*)d_in[1];
    // d_in[2] = idx0_essential — only its COUNT matters (zeros in output)
    const int*   idx1_finite    = (const int*)d_in[3];
    const int*   idx1_essential = (const int*)d_in[4];

    int F0 = in_sizes[1] / 3;   // idx0_finite [F0,3]
    int E0 = in_sizes[2];       // idx0_essential [E0]
    int F1 = in_sizes[3] / 4;   // idx1_finite [F1,4]
    int E1 = in_sizes[4] / 2;   // idx1_essential [E1,2]

    int total_threads = F0 + E0 + F1 + E1;

    const int threads = 128;    // measured optimum
    int blocks = (total_threads + threads - 1) / threads;
    rips_layer_kernel<<<blocks, threads>>>(
        X, idx0_finite, idx1_finite, idx1_essential,
        (float*)d_out, F0, E0, F1, E1);
}